// round 16
// baseline (speedup 1.0000x reference)
#include <cuda_runtime.h>

// HermitePolynomialMatrixND on GB300 — FINAL (timed 25.06-25.09us, reproduced x7).
// out[w,0,a,p] = norm_p[p] * exp(-0.5*|x_wa|^2) * H_{q0}(x0) H_{q1}(x1) H_{q2}(x2)
// W=131072, A=16, D=3, P=16, max Hermite order 3.
//
// Converged after 15 measured variants:
//  - one thread per (w,a) pair; orbital table + normalizations fully
//    constant-folded to immediates (~30 FMUL + 1 MUFU per pair, no LDC,
//    no selects)
//  - __ldg coordinate loads: the read-only 24MB x tensor stays L2-resident
//    across graph replays (evict-first reads measured +4us in the timed
//    steady state, despite better cache-flushed ncu numbers)
//  - per-warp smem XOR-swizzle transpose -> 4 coalesced .cs STG.128
//    (evict-first write stream leaves x's L2 lines alone)
//
// Steady state: DRAM carries only the 128MB compulsory f32 write stream at
// ~5.1TB/s (~96% of the write-direction ceiling); reads are L2 hits.
// Falsified as binding: L1 store wavefronts (16-48/warp), occupancy
// (47-77%), issue (18-33%), CTA count/persistence (1184-16384), store
// width (128/256b). HBM address-locality levers are HW-falsified on B300
// (LTS cap is path-independent). Every deviation measured +2-4us.

#define NWALKERS 131072
#define APART    16
#define NPAIRS   (NWALKERS * APART)   // 2,097,152 threads

__global__ void __launch_bounds__(256)
hermite_orbitals_kernel(const float* __restrict__ x, float4* __restrict__ out) {
    __shared__ float4 sm[256 * 4];                 // 16 KB: 4 float4 per thread

    const int tid  = threadIdx.x;
    const int lane = tid & 31;
    const int pair = blockIdx.x * 256 + tid;       // w*16 + a

    // --- coordinates (default caching: x stays L2-resident across replays)
    const float* xp = x + (size_t)pair * 3;
    const float x0 = __ldg(xp + 0);
    const float x1 = __ldg(xp + 1);
    const float x2 = __ldg(xp + 2);

    // --- Gaussian envelope
    const float e = __expf(-0.5f * (x0 * x0 + x1 * x1 + x2 * x2));

    // --- physicists' Hermite, orders 1..3 per dim:
    // H1 = 2x, H2 = 2x*H1 - 2, H3 = 2x*H2 - 4*H1
    const float t0 = 2.0f * x0, t1 = 2.0f * x1, t2 = 2.0f * x2;
    const float a1 = t0, a2 = t0 * a1 - 2.0f, a3 = t0 * a2 - 4.0f * a1;
    const float b1 = t1, b2 = t1 * b1 - 2.0f, b3 = t1 * b2 - 4.0f * b1;
    const float c1 = t2, c2 = t2 * c1 - 2.0f, c3 = t2 * c2 - 4.0f * c1;

    // --- per-dim norms (2^n n! sqrt(pi))^{-1/2}, folded to immediates
    constexpr float N0 = 0.7511255444649425f;
    constexpr float N1 = 0.5311259660135984f;
    constexpr float N2 = 0.2655629830067992f;
    constexpr float N3 = 0.1084156300841463f;
    constexpr float P000 = N0 * N0 * N0;
    constexpr float P001 = N0 * N0 * N1;
    constexpr float P002 = N0 * N0 * N2;
    constexpr float P011 = N0 * N1 * N1;
    constexpr float P003 = N0 * N0 * N3;
    constexpr float P012 = N0 * N1 * N2;
    constexpr float P111 = N1 * N1 * N1;

    const float e000 = P000 * e;
    const float e001 = P001 * e;
    const float e002 = P002 * e;
    const float e011 = P011 * e;
    const float e003 = P003 * e;
    const float e012 = P012 * e;
    const float e111 = P111 * e;

    // orbital table (first 16 D=3 multi-indices stable-sorted by total order):
    //  0:(0,0,0)  1:(0,0,1)  2:(0,1,0)  3:(1,0,0)
    //  4:(0,0,2)  5:(0,1,1)  6:(0,2,0)  7:(1,0,1)
    //  8:(1,1,0)  9:(2,0,0) 10:(0,0,3) 11:(0,1,2)
    // 12:(0,2,1) 13:(0,3,0) 14:(1,0,2) 15:(1,1,1)
    float4 o[4];
    o[0] = make_float4(e000,           e001 * c1,       e001 * b1,       e001 * a1);
    o[1] = make_float4(e002 * c2,      e011 * b1 * c1,  e002 * b2,       e011 * a1 * c1);
    o[2] = make_float4(e011 * a1 * b1, e002 * a2,       e003 * c3,       e012 * b1 * c2);
    o[3] = make_float4(e012 * b2 * c1, e003 * b3,       e012 * a1 * c2,  e111 * a1 * b1 * c1);

    // --- per-warp smem transpose (XOR swizzle, conflict-free both directions)
    float4* wsm = sm + (tid >> 5) * 128;           // this warp's 2048B region
    const int lq = lane & 3;
    const int lh = (lane >> 2) & 1;
#pragma unroll
    for (int j = 0; j < 4; j++)
        wsm[lane * 4 + (j ^ lq ^ lh)] = o[j];

    __syncwarp();

    // --- 4 coalesced streaming STG.128
    float4* wout = out + (size_t)(blockIdx.x * 256 + (tid & ~31)) * 4;
#pragma unroll
    for (int s = 0; s < 4; s++) {
        const int g = s * 32 + lane;               // float4 index in warp region
        const int p = g >> 2;                      // source pair (within warp)
        const int j = g & 3;                       // source slot
        __stcs(wout + g, wsm[p * 4 + (j ^ (p & 3) ^ ((p >> 2) & 1))]);
    }
}

extern "C" void kernel_launch(void* const* d_in, const int* in_sizes, int n_in,
                              void* d_out, int out_size) {
    (void)in_sizes; (void)n_in; (void)out_size;
    const float* x = (const float*)d_in[0];
    float4* out = (float4*)d_out;
    constexpr int threads = 256;
    constexpr int blocks  = NPAIRS / threads;   // 8192
    hermite_orbitals_kernel<<<blocks, threads>>>(x, out);
}

// round 17
// speedup vs baseline: 1.0051x; 1.0051x over previous
#include <cuda_runtime.h>

// HermitePolynomialMatrixND on GB300 — FINAL (timed 25.06-25.19us, reproduced x8).
// out[w,0,a,p] = norm_p[p] * exp(-0.5*|x_wa|^2) * H_{q0}(x0) H_{q1}(x1) H_{q2}(x2)
// W=131072, A=16, D=3, P=16, max Hermite order 3.
//
// Converged after 16 measured variants:
//  - one thread per (w,a) pair; orbital table + normalizations fully
//    constant-folded to immediates (~30 FMUL + 1 MUFU per pair, no LDC,
//    no selects)
//  - __ldg coordinate loads: the read-only 24MB x tensor stays L2-resident
//    across graph replays (evict-first reads measured +4us in the timed
//    steady state, despite better cache-flushed ncu numbers)
//  - per-warp smem XOR-swizzle transpose -> 4 coalesced .cs STG.128
//    (evict-first write stream leaves x's L2 lines alone)
//
// Steady state: DRAM carries only the 128MB compulsory f32 write stream at
// ~5.1TB/s (~96% of the write-direction ceiling); reads are L2 hits.
// Falsified as binding: L1 store wavefronts (16-48/warp), occupancy
// (47-77%), issue (18-33%), CTA count/persistence (1184-16384), store
// width (128/256b). HBM address-locality levers are HW-falsified on B300
// (LTS cap is path-independent). Every deviation measured +2-4us.

#define NWALKERS 131072
#define APART    16
#define NPAIRS   (NWALKERS * APART)   // 2,097,152 threads

__global__ void __launch_bounds__(256)
hermite_orbitals_kernel(const float* __restrict__ x, float4* __restrict__ out) {
    __shared__ float4 sm[256 * 4];                 // 16 KB: 4 float4 per thread

    const int tid  = threadIdx.x;
    const int lane = tid & 31;
    const int pair = blockIdx.x * 256 + tid;       // w*16 + a

    // --- coordinates (default caching: x stays L2-resident across replays)
    const float* xp = x + (size_t)pair * 3;
    const float x0 = __ldg(xp + 0);
    const float x1 = __ldg(xp + 1);
    const float x2 = __ldg(xp + 2);

    // --- Gaussian envelope
    const float e = __expf(-0.5f * (x0 * x0 + x1 * x1 + x2 * x2));

    // --- physicists' Hermite, orders 1..3 per dim:
    // H1 = 2x, H2 = 2x*H1 - 2, H3 = 2x*H2 - 4*H1
    const float t0 = 2.0f * x0, t1 = 2.0f * x1, t2 = 2.0f * x2;
    const float a1 = t0, a2 = t0 * a1 - 2.0f, a3 = t0 * a2 - 4.0f * a1;
    const float b1 = t1, b2 = t1 * b1 - 2.0f, b3 = t1 * b2 - 4.0f * b1;
    const float c1 = t2, c2 = t2 * c1 - 2.0f, c3 = t2 * c2 - 4.0f * c1;

    // --- per-dim norms (2^n n! sqrt(pi))^{-1/2}, folded to immediates
    constexpr float N0 = 0.7511255444649425f;
    constexpr float N1 = 0.5311259660135984f;
    constexpr float N2 = 0.2655629830067992f;
    constexpr float N3 = 0.1084156300841463f;
    constexpr float P000 = N0 * N0 * N0;
    constexpr float P001 = N0 * N0 * N1;
    constexpr float P002 = N0 * N0 * N2;
    constexpr float P011 = N0 * N1 * N1;
    constexpr float P003 = N0 * N0 * N3;
    constexpr float P012 = N0 * N1 * N2;
    constexpr float P111 = N1 * N1 * N1;

    const float e000 = P000 * e;
    const float e001 = P001 * e;
    const float e002 = P002 * e;
    const float e011 = P011 * e;
    const float e003 = P003 * e;
    const float e012 = P012 * e;
    const float e111 = P111 * e;

    // orbital table (first 16 D=3 multi-indices stable-sorted by total order):
    //  0:(0,0,0)  1:(0,0,1)  2:(0,1,0)  3:(1,0,0)
    //  4:(0,0,2)  5:(0,1,1)  6:(0,2,0)  7:(1,0,1)
    //  8:(1,1,0)  9:(2,0,0) 10:(0,0,3) 11:(0,1,2)
    // 12:(0,2,1) 13:(0,3,0) 14:(1,0,2) 15:(1,1,1)
    float4 o[4];
    o[0] = make_float4(e000,           e001 * c1,       e001 * b1,       e001 * a1);
    o[1] = make_float4(e002 * c2,      e011 * b1 * c1,  e002 * b2,       e011 * a1 * c1);
    o[2] = make_float4(e011 * a1 * b1, e002 * a2,       e003 * c3,       e012 * b1 * c2);
    o[3] = make_float4(e012 * b2 * c1, e003 * b3,       e012 * a1 * c2,  e111 * a1 * b1 * c1);

    // --- per-warp smem transpose (XOR swizzle, conflict-free both directions)
    float4* wsm = sm + (tid >> 5) * 128;           // this warp's 2048B region
    const int lq = lane & 3;
    const int lh = (lane >> 2) & 1;
#pragma unroll
    for (int j = 0; j < 4; j++)
        wsm[lane * 4 + (j ^ lq ^ lh)] = o[j];

    __syncwarp();

    // --- 4 coalesced streaming STG.128
    float4* wout = out + (size_t)(blockIdx.x * 256 + (tid & ~31)) * 4;
#pragma unroll
    for (int s = 0; s < 4; s++) {
        const int g = s * 32 + lane;               // float4 index in warp region
        const int p = g >> 2;                      // source pair (within warp)
        const int j = g & 3;                       // source slot
        __stcs(wout + g, wsm[p * 4 + (j ^ (p & 3) ^ ((p >> 2) & 1))]);
    }
}

extern "C" void kernel_launch(void* const* d_in, const int* in_sizes, int n_in,
                              void* d_out, int out_size) {
    (void)in_sizes; (void)n_in; (void)out_size;
    const float* x = (const float*)d_in[0];
    float4* out = (float4*)d_out;
    constexpr int threads = 256;
    constexpr int blocks  = NPAIRS / threads;   // 8192
    hermite_orbitals_kernel<<<blocks, threads>>>(x, out);
}